// round 2
// baseline (speedup 1.0000x reference)
#include <cuda_runtime.h>
#include <cstdint>
#include <cstddef>

#define Lc   1024
#define Bc   8192
#define Rv   8          // batches per warp

// epsT[i*256 + d*128 + m]
__device__ float  g_epsT[Lc * 256];
// xf2[i*Bc + b] = {x, x} as float
__device__ float2 g_xf2[(size_t)Lc * Bc];

__global__ void prep_eps(const float* __restrict__ eps) {
    int idx = blockIdx.x * 256 + threadIdx.x;      // idx = i*256 + dm
    int dm = idx & 255;
    int i  = idx >> 8;
    g_epsT[idx] = eps[(dm << 10) + i];
}

__global__ void prep_x(const int* __restrict__ x) {
    __shared__ float tile[32][33];
    int bT = blockIdx.x * 32, iT = blockIdx.y * 32;
    int tx = threadIdx.x, ty = threadIdx.y;        // block (32, 8)
#pragma unroll
    for (int k = 0; k < 4; k++) {
        int r = ty + 8 * k;
        tile[r][tx] = (float)x[(size_t)(bT + r) * Lc + iT + tx];
    }
    __syncthreads();
#pragma unroll
    for (int k = 0; k < 4; k++) {
        int r = ty + 8 * k;
        float v = tile[tx][r];
        g_xf2[(size_t)(iT + r) * Bc + bT + tx] = make_float2(v, v);
    }
}

static __device__ __forceinline__ uint64_t mul2(uint64_t a, uint64_t b) {
    uint64_t d; asm("mul.rn.f32x2 %0, %1, %2;" : "=l"(d) : "l"(a), "l"(b)); return d;
}
static __device__ __forceinline__ uint64_t fma2(uint64_t a, uint64_t b, uint64_t c) {
    uint64_t d; asm("fma.rn.f32x2 %0, %1, %2, %3;" : "=l"(d) : "l"(a), "l"(b), "l"(c)); return d;
}
static __device__ __forceinline__ float hadd2(uint64_t v) {
    float x, y; asm("mov.b64 {%0,%1}, %2;" : "=f"(x), "=f"(y) : "l"(v)); return x + y;
}
static __device__ __forceinline__ float ex2f(float x) {
    float y; asm("ex2.approx.ftz.f32 %0, %1;" : "=f"(y) : "f"(x)); return y;
}
static __device__ __forceinline__ float lg2f(float x) {
    float y; asm("lg2.approx.ftz.f32 %0, %1;" : "=f"(y) : "f"(x)); return y;
}

__global__ __launch_bounds__(128, 1)
void arqgps_main(float* __restrict__ out) {
    const int l     = threadIdx.x & 31;
    const int warpG = blockIdx.x * 4 + (threadIdx.x >> 5);
    const int b0    = warpG * Rv;
    // after butterfly, lane l holds value v = bitrev4(l&15); v = 2*j + d
    const int jmap  = ((l & 1) << 2) | (l & 2) | ((l >> 2) & 1);
    const int dmap  = (l >> 3) & 1;

    const uint64_t ONE2  = 0x3f8000003f800000ull;
    const uint64_t NEG12 = 0xbf800000bf800000ull;

    uint64_t g0[Rv], g1[Rv];
#pragma unroll
    for (int j = 0; j < Rv; j++) { g0[j] = ONE2; g1[j] = ONE2; }

    float acc = 0.0f;
    int cnt0 = 0;

    const ulonglong2* ebase = (const ulonglong2*)g_epsT;             // 64 x 16B per step
    const ulonglong2* xb    = (const ulonglong2*)(g_xf2 + b0);       // 4096 x 16B per step
    const float*      xsp   = (const float*)g_xf2 + (size_t)2 * (b0 + jmap);

#pragma unroll 2
    for (int i = 0; i < Lc; i++) {
        ulonglong2 E0  = __ldg(ebase + (size_t)i * 64 + l);          // d=0, m 4l..4l+3
        ulonglong2 E1  = __ldg(ebase + (size_t)i * 64 + 32 + l);     // d=1
        ulonglong2 X01 = __ldg(xb + (size_t)i * 4096 + 0);
        ulonglong2 X23 = __ldg(xb + (size_t)i * 4096 + 1);
        ulonglong2 X45 = __ldg(xb + (size_t)i * 4096 + 2);
        ulonglong2 X67 = __ldg(xb + (size_t)i * 4096 + 3);
        float xsel     = __ldg(xsp + (size_t)i * 2 * Bc);

        uint64_t xs2[Rv] = {X01.x, X01.y, X23.x, X23.y, X45.x, X45.y, X67.x, X67.y};

        // esel = e0 + x*(e1-e0); ed = e1 - e0 via fma with {-1,-1}
        uint64_t eda = fma2(E0.x, NEG12, E1.x);
        uint64_t edb = fma2(E0.y, NEG12, E1.y);

        float vals[16];
#pragma unroll
        for (int j = 0; j < Rv; j++) {
            uint64_t p0 = fma2(E0.y, g1[j], mul2(E0.x, g0[j]));
            uint64_t p1 = fma2(E1.y, g1[j], mul2(E1.x, g0[j]));
            g0[j] = mul2(g0[j], fma2(xs2[j], eda, E0.x));
            g1[j] = mul2(g1[j], fma2(xs2[j], edb, E0.y));
            vals[2 * j]     = hadd2(p0);
            vals[2 * j + 1] = hadd2(p1);
        }

        // butterfly reduce: 16 values over 32 lanes
#pragma unroll
        for (int lev = 0; lev < 4; lev++) {
            const int off = 1 << lev;
            const int h   = 8 >> lev;
            const bool hi = (l >> lev) & 1;
#pragma unroll
            for (int j = 0; j < h; j++) {
                float a = vals[j], b = vals[j + h];
                float keep = hi ? b : a;
                float send = hi ? a : b;
                float recv = __shfl_xor_sync(0xffffffffu, send, off);
                vals[j] = keep + recv;
            }
        }
        float mine  = vals[0] + __shfl_xor_sync(0xffffffffu, vals[0], 16);
        float other = __shfl_xor_sync(0xffffffffu, mine, 8);

        float s0 = dmap ? other : mine;
        float s1 = dmap ? mine  : other;

        bool  x1  = (xsel > 0.5f);
        float lps = x1 ? s1 : s0;
        float mx  = fmaxf(s0, s1);
        float dd  = fabsf(s0 - s1);
        float z   = ex2f(dd * -2.8853902f);                 // exp(-2*dd)
        float term = (lps - mx) - 0.34657359f * lg2f(1.0f + z);

        int cOther = x1 ? cnt0 : (i - cnt0);
        if (cOther >= 512) term = 0.0f;
        acc += term;
        cnt0 += x1 ? 0 : 1;
    }

    if (l < 8) out[b0 + jmap] = acc;
}

extern "C" void kernel_launch(void* const* d_in, const int* in_sizes, int n_in,
                              void* d_out, int out_size) {
    (void)n_in; (void)out_size;
    const int*   inputs;
    const float* eps;
    if (in_sizes[0] == Bc * Lc) {
        inputs = (const int*)d_in[0];
        eps    = (const float*)d_in[1];
    } else {
        inputs = (const int*)d_in[1];
        eps    = (const float*)d_in[0];
    }
    float* out = (float*)d_out;

    prep_eps<<<Lc, 256>>>(eps);
    dim3 bx(32, 8);
    dim3 gx(Bc / 32, Lc / 32);
    prep_x<<<gx, bx>>>(inputs);

    arqgps_main<<<Bc / (Rv * 4), 128>>>(out);
}

// round 3
// speedup vs baseline: 1.3141x; 1.3141x over previous
#include <cuda_runtime.h>
#include <cstdint>
#include <cstddef>

#define Lc 1024
#define Bc 8192
#define CC 64           // steps per smem chunk
#define XPITCH 33       // padded float2 row pitch for xs

// epsT[i*256 + d*128 + m]
__device__ float g_epsT[Lc * 256];

__global__ void prep_eps(const float* __restrict__ eps) {
    int idx = blockIdx.x * 256 + threadIdx.x;   // idx = i*256 + dm
    int dm = idx & 255;
    int i  = idx >> 8;
    g_epsT[idx] = eps[(dm << 10) + i];          // eps[(d*128+m)*1024 + i]
}

static __device__ __forceinline__ uint64_t mul2(uint64_t a, uint64_t b) {
    uint64_t d; asm("mul.rn.f32x2 %0, %1, %2;" : "=l"(d) : "l"(a), "l"(b)); return d;
}
static __device__ __forceinline__ uint64_t fma2(uint64_t a, uint64_t b, uint64_t c) {
    uint64_t d; asm("fma.rn.f32x2 %0, %1, %2, %3;" : "=l"(d) : "l"(a), "l"(b), "l"(c)); return d;
}
static __device__ __forceinline__ float hadd2(uint64_t v) {
    float x, y; asm("mov.b64 {%0,%1}, %2;" : "=f"(x), "=f"(y) : "l"(v)); return x + y;
}
static __device__ __forceinline__ float lo32f(uint64_t v) {
    float x, y; asm("mov.b64 {%0,%1}, %2;" : "=f"(x), "=f"(y) : "l"(v)); return x;
}
static __device__ __forceinline__ float ex2f(float x) {
    float y; asm("ex2.approx.ftz.f32 %0, %1;" : "=f"(y) : "f"(x)); return y;
}
static __device__ __forceinline__ float lg2f(float x) {
    float y; asm("lg2.approx.ftz.f32 %0, %1;" : "=f"(y) : "f"(x)); return y;
}

__global__ __launch_bounds__(256, 2)
void arqgps_main(const int* __restrict__ inputs, float* __restrict__ out) {
    extern __shared__ float smemf[];
    float*  es = smemf;                              // CC*256 floats (64 KB)
    float2* xs = (float2*)(smemf + CC * 256);        // CC*XPITCH float2 (16.9 KB)

    const int t    = threadIdx.x;
    const int l    = t & 31;
    const int w    = t >> 5;            // warp 0..7
    const int wb   = w << 2;            // warp's batch base within block (4 per warp)
    const int b0   = blockIdx.x * 32;
    const int perm = (l >> 1) & 3;      // lane's slot->batch XOR key; also its term-batch

    const uint64_t ONE2  = 0x3f8000003f800000ull;
    const uint64_t NEG12 = 0xbf800000bf800000ull;

    uint64_t gx[4], gy[4];
#pragma unroll
    for (int sp = 0; sp < 4; sp++) { gx[sp] = ONE2; gy[sp] = ONE2; }

    float acc  = 0.0f;
    int   cnt0 = 0;

    for (int chunk = 0; chunk < Lc / CC; chunk++) {
        __syncthreads();
        // ---- stage epsilon chunk: natural layout es[i*256 + d*128 + m] ----
        {
            const float4* src = (const float4*)(g_epsT + chunk * (CC * 256));
            float4*       dst = (float4*)es;
#pragma unroll
            for (int it = 0; it < 16; it++)
                dst[t + it * 256] = src[t + it * 256];
        }
        // ---- stage inputs chunk as float2{x,x}: xs[i*XPITCH + bl] ----
        {
            int bl = t >> 3;                     // 0..31
            int i0 = (t & 7) << 3;               // 0..56 step 8
            const int* ip = inputs + (size_t)(b0 + bl) * Lc + chunk * CC + i0;
            int4 a = *(const int4*)ip;
            int4 b = *(const int4*)(ip + 4);
            int vv[8] = {a.x, a.y, a.z, a.w, b.x, b.y, b.z, b.w};
#pragma unroll
            for (int k = 0; k < 8; k++) {
                float f = (float)vv[k];
                xs[(i0 + k) * XPITCH + bl] = make_float2(f, f);
            }
        }
        __syncthreads();

#pragma unroll 2
        for (int ii = 0; ii < CC; ii++) {
            const int i = chunk * CC + ii;
            const float* ep = es + ii * 256;
            ulonglong2 E0 = *(const ulonglong2*)(ep + 4 * l);         // d=0, m 4l..4l+3
            ulonglong2 E1 = *(const ulonglong2*)(ep + 128 + 4 * l);   // d=1
            uint64_t edx = fma2(E0.x, NEG12, E1.x);                   // E1-E0
            uint64_t edy = fma2(E0.y, NEG12, E1.y);

            float v[8];
            float xsel0 = 0.0f;
#pragma unroll
            for (int sp = 0; sp < 4; sp++) {
                const int jb = sp ^ perm;                             // batch this slot tracks
                uint64_t x2 = *(const uint64_t*)&xs[ii * XPITCH + wb + jb];
                if (sp == 0) xsel0 = lo32f(x2);                       // x of lane's term-batch
                uint64_t p0 = fma2(E0.y, gy[sp], mul2(E0.x, gx[sp]));
                uint64_t p1 = fma2(E1.y, gy[sp], mul2(E1.x, gx[sp]));
                gx[sp] = mul2(gx[sp], fma2(x2, edx, E0.x));           // g *= E_{x}
                gy[sp] = mul2(gy[sp], fma2(x2, edy, E0.y));
                v[2 * sp]     = hadd2(p0);
                v[2 * sp + 1] = hadd2(p1);
            }

            // XOR-permuted butterfly: slot s holds (batch (s>>1)^perm, d=s&1).
            // Every level is sel-free: partner's slot s^off holds the SAME value index.
#pragma unroll
            for (int s = 0; s < 4; s++) v[s] += __shfl_xor_sync(0xffffffffu, v[s ^ 4], 4);
#pragma unroll
            for (int s = 0; s < 2; s++) v[s] += __shfl_xor_sync(0xffffffffu, v[s ^ 2], 2);
            v[0] += __shfl_xor_sync(0xffffffffu, v[0], 1);
            v[1] += __shfl_xor_sync(0xffffffffu, v[1], 1);
            v[0] += __shfl_xor_sync(0xffffffffu, v[0], 8);
            v[1] += __shfl_xor_sync(0xffffffffu, v[1], 8);
            v[0] += __shfl_xor_sync(0xffffffffu, v[0], 16);
            v[1] += __shfl_xor_sync(0xffffffffu, v[1], 16);

            const float s0 = v[0];      // lp_{d=0} of batch 'perm'
            const float s1 = v[1];      // lp_{d=1}

            const bool  x1  = (xsel0 > 0.5f);
            const float lps = x1 ? s1 : s0;
            const float mx  = fmaxf(s0, s1);
            const float dd  = fabsf(s0 - s1);
            const float z   = ex2f(dd * -2.8853902f);                 // exp(-2*dd)
            float term = (lps - mx) - 0.34657359f * lg2f(1.0f + z);

            const int cOther = x1 ? cnt0 : (i - cnt0);                // count of other spin so far
            if (cOther >= 512) term = 0.0f;
            acc += term;
            cnt0 += x1 ? 0 : 1;
        }
    }

    if ((l & 9) == 0 && l < 8)          // lanes 0,2,4,6 -> batches 0..3 of this warp
        out[b0 + wb + (l >> 1)] = acc;
}

extern "C" void kernel_launch(void* const* d_in, const int* in_sizes, int n_in,
                              void* d_out, int out_size) {
    (void)n_in; (void)out_size;
    const int*   inputs;
    const float* eps;
    if (in_sizes[0] == Bc * Lc) {
        inputs = (const int*)d_in[0];
        eps    = (const float*)d_in[1];
    } else {
        inputs = (const int*)d_in[1];
        eps    = (const float*)d_in[0];
    }
    float* out = (float*)d_out;

    prep_eps<<<Lc, 256>>>(eps);

    size_t smem = (size_t)CC * 256 * 4 + (size_t)CC * XPITCH * 8;   // 82432 B
    cudaFuncSetAttribute(arqgps_main,
                         cudaFuncAttributeMaxDynamicSharedMemorySize, (int)smem);
    arqgps_main<<<Bc / 32, 256, smem>>>(inputs, out);
}